// round 12
// baseline (speedup 1.0000x reference)
#include <cuda_runtime.h>
#include <math.h>

#define NFFT   512
#define HOP    480
#define NBINS  257
#define BATCH  8
#define LSIG   88200
#define NT     184
#define NFR    2                      // frames per block (1 group x 2 frames)
#define NTHREADS 64
#define NBLKS  (BATCH * NT / NFR)     // 736 blocks
#define BARKMID 12.37

__device__ float g_partial[NBLKS];
__device__ unsigned int g_count = 0;

// ===========================================================================
// constexpr fp64 math (compile-time) — series-based, ~1e-14 accurate
// ===========================================================================
constexpr double c_sqrt(double x) {
    double g = x > 1.0 ? x : 1.0;
    for (int i = 0; i < 80; i++) g = 0.5 * (g + x / g);
    return g;
}
constexpr double c_exp(double x) {
    const double ln2 = 0.69314718055994530942;
    int k = (int)(x / ln2 + (x >= 0 ? 0.5 : -0.5));
    double r = x - (double)k * ln2;
    double term = 1.0, sum = 1.0;
    for (int i = 1; i <= 22; i++) { term *= r / (double)i; sum += term; }
    double p = 1.0;
    if (k >= 0) { for (int i = 0; i < k;  i++) p *= 2.0; }
    else        { for (int i = 0; i < -k; i++) p *= 0.5; }
    return sum * p;
}
constexpr double c_log(double x) {
    int k = 0; double m = x;
    while (m >= 2.0) { m *= 0.5; k++; }
    while (m < 1.0)  { m *= 2.0; k--; }
    double t = (m - 1.0) / (m + 1.0), t2 = t * t, term = t, sum = 0.0;
    for (int i = 0; i < 45; i++) { sum += term / (double)(2 * i + 1); term *= t2; }
    return 2.0 * sum + (double)k * 0.69314718055994530942;
}
constexpr double c_pow(double x, double y) { return c_exp(y * c_log(x)); }
constexpr double c_atan(double x) {
    if (x < 0.0) return -c_atan(-x);
    if (x > 1.0) return 1.57079632679489661923 - c_atan(1.0 / x);
    double x1 = x  / (1.0 + c_sqrt(1.0 + x  * x));
    double x2 = x1 / (1.0 + c_sqrt(1.0 + x1 * x1));
    double t2 = x2 * x2, term = x2, sum = 0.0;
    for (int i = 0; i < 26; i++) {
        sum += ((i & 1) ? -term : term) / (double)(2 * i + 1);
        term *= t2;
    }
    return 4.0 * sum;
}
constexpr double c_cospi(double x) {
    double y = x;
    while (y >= 2.0) y -= 2.0;
    while (y < 0.0)  y += 2.0;
    double sign = 1.0;
    if (y > 1.0) y = 2.0 - y;
    if (y > 0.5) { y = 1.0 - y; sign = -1.0; }
    double a = y * 3.14159265358979323846;
    double a2 = a * a, term = 1.0, sum = 0.0;
    for (int i = 0; i < 16; i++) { sum += term; term *= -a2 / (double)((2 * i + 1) * (2 * i + 2)); }
    return sign * sum;
}
constexpr double c_sinpi(double x) { return c_cospi(x - 0.5); }
constexpr double c_bark(int i) {
    double freq = (double)i * (44100.0 / 512.0);
    double r = freq / 7500.0;
    return 13.0 * c_atan(0.00076 * freq) + 3.5 * c_atan(r * r);
}

// Flat table blob: win[512] | tw[7][64] (float2) | cA dA cB dB ath (260 ea)
#define OFF_WIN 0
#define OFF_TW  512
#define OFF_CA  1408
#define OFF_DA  1668
#define OFF_CB  1928
#define OFF_DB  2188
#define OFF_ATH 2448
#define TABN4   2708
#define NTW     (7 * 64)              // twiddle float2 count

struct AllTabs { alignas(16) float v[TABN4]; };

constexpr AllTabs mk_tabs() {
    AllTabs t{};
    for (int i = 0; i < NFFT; i++)
        t.v[OFF_WIN + i] = (float)(0.5 * (1.0 - c_cospi((double)i / 256.0)));
    for (int r = 0; r < 7; r++)
        for (int j = 0; j < 64; j++) {
            double ang = (double)(j * (r + 1)) / 256.0;
            t.v[OFF_TW + 2 * (r * 64 + j) + 0] = (float)c_cospi(ang);
            t.v[OFF_TW + 2 * (r * 64 + j) + 1] = (float)(-c_sinpi(ang));  // conj
        }
    const double LN10 = 2.30258509299404568402;
    for (int i = 0; i < NBINS; i++) {
        double d = (c_bark(i) - BARKMID) * LN10;
        t.v[OFF_CA + i] = (float)c_exp( 1.7 * d);
        t.v[OFF_DA + i] = (float)c_exp(-1.7 * d);
        t.v[OFF_CB + i] = (float)c_exp(-2.7 * d);
        t.v[OFF_DB + i] = (float)c_exp( 2.7 * d);
        double freq = (double)i * (44100.0 / 512.0);
        double f = freq > 1e-6 ? freq : 1e-6;
        double fk = f / 1000.0;
        double ath_db = 3.64 * c_pow(fk, -0.8)
                      - 6.5 * c_exp(-0.6 * (fk - 3.3) * (fk - 3.3))
                      + 0.001 * fk * fk * fk * fk;
        if (ath_db > 100.0) ath_db = 100.0;
        if (ath_db < -100.0) ath_db = -100.0;
        double a = c_exp(ath_db * 0.1 * LN10);
        if (a < 1e-12) a = 1e-12;
        t.v[OFF_ATH + i] = (float)a;
    }
    return t;
}
__device__ const AllTabs g_tabs = mk_tabs();

// ===========================================================================
__device__ __forceinline__ float2 cadd(float2 a, float2 b) { return make_float2(a.x + b.x, a.y + b.y); }
__device__ __forceinline__ float2 csub(float2 a, float2 b) { return make_float2(a.x - b.x, a.y - b.y); }
__device__ __forceinline__ float2 cmul(float2 a, float2 b) {
    return make_float2(fmaf(a.x, b.x, -a.y * b.y), fmaf(a.x, b.y, a.y * b.x));
}

__device__ __forceinline__ void dft8(float2* x) {
    const float C = 0.70710678118654752f;
    float2 a0 = cadd(x[0], x[4]), a4 = csub(x[0], x[4]);
    float2 a2 = cadd(x[2], x[6]), a6 = csub(x[2], x[6]);
    float2 a1 = cadd(x[1], x[5]), a5 = csub(x[1], x[5]);
    float2 a3 = cadd(x[3], x[7]), a7 = csub(x[3], x[7]);
    float2 b0 = cadd(a0, a2), b2 = csub(a0, a2);
    float2 b1 = cadd(a1, a3), b3 = csub(a1, a3);
    float2 b4 = make_float2(a4.x + a6.y, a4.y - a6.x);
    float2 b6 = make_float2(a4.x - a6.y, a4.y + a6.x);
    float2 b5 = make_float2(a5.x + a7.y, a5.y - a7.x);
    float2 b7 = make_float2(a5.x - a7.y, a5.y + a7.x);
    x[0] = cadd(b0, b1);  x[4] = csub(b0, b1);
    x[2] = make_float2(b2.x + b3.y, b2.y - b3.x);
    x[6] = make_float2(b2.x - b3.y, b2.y + b3.x);
    float2 t5 = make_float2(C * (b5.x + b5.y), C * (b5.y - b5.x));
    x[1] = cadd(b4, t5);  x[5] = csub(b4, t5);
    float2 t7 = make_float2(C * (b7.y - b7.x), -C * (b7.x + b7.y));
    x[3] = cadd(b6, t7);  x[7] = csub(b6, t7);
}

#define PHYS(i) ((i) + ((i) >> 3))

__global__ __launch_bounds__(NTHREADS) void pam_kernel(
    const float* __restrict__ pred, const float* __restrict__ tgt,
    float* __restrict__ out)
{
    __shared__ float4 Zs[576];                  // .xy frame A, .zw frame B
    __shared__ float2 sTw[NTW];
    __shared__ __align__(16) float pts[NFR][260];
    __shared__ float sAg[NFR], sBg[NFR];
    __shared__ float redw[2];
    __shared__ int   s_last;

    const int j    = threadIdx.x;          // 0..63
    const int lane = j & 31;
    const int fw   = j >> 5;               // warp within block (0/1)

    const int b = blockIdx.y;
    const int tbA = (NFR * blockIdx.x) * HOP - (NFFT / 2);

    // ---- early global loads: window taps + psycho tables (no dependencies,
    //      front-batched by ptxas, hidden behind everything below) ----
    float wv[8];
    #pragma unroll
    for (int h = 0; h < 8; h++) wv[h] = g_tabs.v[OFF_WIN + h * 64 + j];
    const float4 cA4 = *(const float4*)&g_tabs.v[OFF_CA  + 4 * j];
    const float4 cB4 = *(const float4*)&g_tabs.v[OFF_CB  + 4 * j];
    const float4 dA4 = *(const float4*)&g_tabs.v[OFF_DA  + 4 * j];
    const float4 dB4 = *(const float4*)&g_tabs.v[OFF_DB  + 4 * j];
    const float4 at4 = *(const float4*)&g_tabs.v[OFF_ATH + 4 * j];
    const float dA256 = g_tabs.v[OFF_DA + 256];
    const float at256 = g_tabs.v[OFF_ATH + 256];

    // ---- stage twiddles to shared (3.5KB, coalesced float4) ----
    {
        const float4* src = (const float4*)&g_tabs.v[OFF_TW];
        float4* dst = (float4*)sTw;
        #pragma unroll
        for (int i = j; i < NTW / 2; i += NTHREADS) dst[i] = src[i];
    }

    // ---- prefetch both frames' samples (reflect pad) ----
    const float* xp = pred + b * LSIG;
    const float* xt = tgt  + b * LSIG;
    float vxA[8], vyA[8], vxB[8], vyB[8];
    #pragma unroll
    for (int h = 0; h < 8; h++) {
        int n  = h * 64 + j;
        int gA = tbA + n;
        int gB = gA + HOP;
        if (gA < 0) gA = -gA;
        if (gA >= LSIG) gA = 2 * LSIG - 2 - gA;
        if (gB >= LSIG) gB = 2 * LSIG - 2 - gB;
        vxA[h] = xp[gA]; vyA[h] = xt[gA];
        vxB[h] = xp[gB]; vyB[h] = xt[gB];
    }
    #pragma unroll
    for (int h = 0; h < 8; h++) {
        int n = h * 64 + j;
        float w = wv[h];
        Zs[PHYS(n)] = make_float4(vxA[h] * w, vyA[h] * w, vxB[h] * w, vyB[h] * w);
    }
    __syncthreads();

    // ---- pass 0: Lc=512, stride 64, twiddle tw[r][j] ----
    {
        float2 xa[8], xb[8];
        #pragma unroll
        for (int m = 0; m < 8; m++) {
            float4 v = Zs[PHYS(j + (m << 6))];
            xa[m] = make_float2(v.x, v.y);
            xb[m] = make_float2(v.z, v.w);
        }
        dft8(xa); dft8(xb);
        #pragma unroll
        for (int r = 1; r < 8; r++) {
            float2 w = sTw[(r - 1) * 64 + j];
            xa[r] = cmul(xa[r], w);
            xb[r] = cmul(xb[r], w);
        }
        #pragma unroll
        for (int r = 0; r < 8; r++)
            Zs[PHYS(j + (r << 6))] = make_float4(xa[r].x, xa[r].y, xb[r].x, xb[r].y);
    }
    __syncthreads();

    // ---- pass 1: Lc=64, stride 8, twiddle W64^(p*r) = tw[r][8p] ----
    {
        int p = j & 7;
        int base = ((j >> 3) << 6) + p;
        float2 xa[8], xb[8];
        #pragma unroll
        for (int m = 0; m < 8; m++) {
            float4 v = Zs[PHYS(base + (m << 3))];
            xa[m] = make_float2(v.x, v.y);
            xb[m] = make_float2(v.z, v.w);
        }
        dft8(xa); dft8(xb);
        #pragma unroll
        for (int r = 1; r < 8; r++) {
            float2 w = sTw[(r - 1) * 64 + (p << 3)];
            xa[r] = cmul(xa[r], w);
            xb[r] = cmul(xb[r], w);
        }
        #pragma unroll
        for (int r = 0; r < 8; r++)
            Zs[PHYS(base + (r << 3))] = make_float4(xa[r].x, xa[r].y, xb[r].x, xb[r].y);
    }
    __syncthreads();

    // ---- pass 2: Lc=8, contiguous (phys = 9j+m), no twiddle ----
    {
        float2 xa[8], xb[8];
        #pragma unroll
        for (int m = 0; m < 8; m++) {
            float4 v = Zs[9 * j + m];
            xa[m] = make_float2(v.x, v.y);
            xb[m] = make_float2(v.z, v.w);
        }
        dft8(xa); dft8(xb);
        #pragma unroll
        for (int m = 0; m < 8; m++)
            Zs[9 * j + m] = make_float4(xa[m].x, xa[m].y, xb[m].x, xb[m].y);
    }
    __syncthreads();

    // ---- unpack both real spectra for both frames; bins 4j..4j+3 ----
    float ppA[4], ptA[4], ppB[4], ptB[4];
    #pragma unroll
    for (int i = 0; i < 4; i++) {
        int k  = 4 * j + i;
        int pk = ((k & 7) << 6) | (k & 56) | (k >> 6);
        int kc = (NFFT - k) & (NFFT - 1);
        int pc = ((kc & 7) << 6) | (kc & 56) | (kc >> 6);
        float4 zk = Zs[PHYS(pk)];
        float4 zc = Zs[PHYS(pc)];
        {
            float spr = zk.x + zc.x, spi = zk.y - zc.y;
            float str = zk.y + zc.y, sti = zc.x - zk.x;
            ppA[i] = 0.25f * (spr * spr + spi * spi) + 1e-12f;
            ptA[i] = 0.25f * (str * str + sti * sti) + 1e-12f;
        }
        {
            float spr = zk.z + zc.z, spi = zk.w - zc.w;
            float str = zk.w + zc.w, sti = zc.z - zk.z;
            ppB[i] = 0.25f * (spr * spr + spi * spi) + 1e-12f;
            ptB[i] = 0.25f * (str * str + sti * sti) + 1e-12f;
        }
    }
    *(float4*)&pts[0][4 * j] = make_float4(ptA[0], ptA[1], ptA[2], ptA[3]);
    *(float4*)&pts[1][4 * j] = make_float4(ptB[0], ptB[1], ptB[2], ptB[3]);

    float ppA6 = 0.f, ptA6 = 0.f, ppB6 = 0.f, ptB6 = 0.f;
    if (j == 63) {                          // bin 256 at digit-reversed pos 4
        float4 z6 = Zs[PHYS(4)];
        ppA6 = z6.x * z6.x + 1e-12f;  ptA6 = z6.y * z6.y + 1e-12f;
        ppB6 = z6.z * z6.z + 1e-12f;  ptB6 = z6.w * z6.w + 1e-12f;
        pts[0][256] = ptA6;
        pts[1][256] = ptB6;
    }
    __syncthreads();

    // ---- tonal detection + scaled linear masker terms (both frames) ----
    const float cAa[4] = { cA4.x, cA4.y, cA4.z, cA4.w };
    const float cBa[4] = { cB4.x, cB4.y, cB4.z, cB4.w };

    float aA[4], bA[4], aB[4], bB[4];
    {
        float pprevA = (j == 0) ? 3.4e38f : pts[0][4 * j - 1];
        float pnextA = pts[0][4 * j + 4];
        float pprevB = (j == 0) ? 3.4e38f : pts[1][4 * j - 1];
        float pnextB = pts[1][4 * j + 4];
        #pragma unroll
        for (int i = 0; i < 4; i++) {
            int k = 4 * j + i;
            float pA = ptA[i];
            float plA = (i == 0) ? pprevA : ptA[i - 1];
            float prA = (i == 3) ? pnextA : ptA[i + 1];
            bool tA = (k >= 1) && (pA > plA) && (pA > prA) && (pA >= 1e-4f);
            aA[i] = tA ? pA * cAa[i] : 0.0f;
            bA[i] = tA ? pA * cBa[i] : 0.0f;
            float pB = ptB[i];
            float plB = (i == 0) ? pprevB : ptB[i - 1];
            float prB = (i == 3) ? pnextB : ptB[i + 1];
            bool tB = (k >= 1) && (pB > plB) && (pB > prB) && (pB >= 1e-4f);
            aB[i] = tB ? pB * cAa[i] : 0.0f;
            bB[i] = tB ? pB * cBa[i] : 0.0f;
        }
    }

    // local prefix/suffix per frame
    float paA0 = aA[0], paA1 = fmaxf(paA0, aA[1]), paA2 = fmaxf(paA1, aA[2]), paA3 = fmaxf(paA2, aA[3]);
    float sbA3 = bA[3], sbA2 = fmaxf(sbA3, bA[2]), sbA1 = fmaxf(sbA2, bA[1]), sbA0 = fmaxf(sbA1, bA[0]);
    float paB0 = aB[0], paB1 = fmaxf(paB0, aB[1]), paB2 = fmaxf(paB1, aB[2]), paB3 = fmaxf(paB2, aB[3]);
    float sbB3 = bB[3], sbB2 = fmaxf(sbB3, bB[2]), sbB1 = fmaxf(sbB2, bB[1]), sbB0 = fmaxf(sbB1, bB[0]);

    // warp inclusive scans (forward for A-terms, reverse for B-terms), both frames
    float incA = paA3, incB = paB3;
    #pragma unroll
    for (int off = 1; off < 32; off <<= 1) {
        float oA = __shfl_up_sync(0xffffffffu, incA, off);
        float oB = __shfl_up_sync(0xffffffffu, incB, off);
        if (lane >= off) { incA = fmaxf(incA, oA); incB = fmaxf(incB, oB); }
    }
    float exAA = __shfl_up_sync(0xffffffffu, incA, 1);
    float exAB = __shfl_up_sync(0xffffffffu, incB, 1);
    if (lane == 0) { exAA = 0.0f; exAB = 0.0f; }
    if (fw == 0 && lane == 31) { sAg[0] = incA; sAg[1] = incB; }

    float rincA = sbA0, rincB = sbB0;
    #pragma unroll
    for (int off = 1; off < 32; off <<= 1) {
        float oA = __shfl_down_sync(0xffffffffu, rincA, off);
        float oB = __shfl_down_sync(0xffffffffu, rincB, off);
        if (lane + off < 32) { rincA = fmaxf(rincA, oA); rincB = fmaxf(rincB, oB); }
    }
    float exBA = __shfl_down_sync(0xffffffffu, rincA, 1);
    float exBB = __shfl_down_sync(0xffffffffu, rincB, 1);
    if (lane == 31) { exBA = 0.0f; exBB = 0.0f; }
    if (fw == 1 && lane == 0) { sBg[0] = rincA; sBg[1] = rincB; }
    __syncthreads();

    if (fw == 1) { exAA = fmaxf(exAA, sAg[0]); exAB = fmaxf(exAB, sAg[1]); }
    if (fw == 0) { exBA = fmaxf(exBA, sBg[0]); exBB = fmaxf(exBB, sBg[1]); }

    // ---- per-bin masking, weights, error (both frames) ----
    float ApA[4] = { fmaxf(exAA, paA0), fmaxf(exAA, paA1), fmaxf(exAA, paA2), fmaxf(exAA, paA3) };
    float BsA[4] = { fmaxf(exBA, sbA0), fmaxf(exBA, sbA1), fmaxf(exBA, sbA2), fmaxf(exBA, sbA3) };
    float ApB[4] = { fmaxf(exAB, paB0), fmaxf(exAB, paB1), fmaxf(exAB, paB2), fmaxf(exAB, paB3) };
    float BsB[4] = { fmaxf(exBB, sbB0), fmaxf(exBB, sbB1), fmaxf(exBB, sbB2), fmaxf(exBB, sbB3) };

    const float dAa[4] = { dA4.x, dA4.y, dA4.z, dA4.w };
    const float dBa[4] = { dB4.x, dB4.y, dB4.z, dB4.w };
    const float ata[4] = { at4.x, at4.y, at4.z, at4.w };

    float contrib = 0.0f;
    #pragma unroll
    for (int i = 0; i < 4; i++) {
        {
            float masking = fmaxf(ApA[i] * dAa[i], BsA[i] * dBa[i]);
            float combined = masking + ata[i];
            float w  = __log10f(ptA[i] / (combined + 1e-12f) + 1.0f);
            float d  = sqrtf(ppA[i]) - sqrtf(ptA[i]);
            contrib += w * d * d;
        }
        {
            float masking = fmaxf(ApB[i] * dAa[i], BsB[i] * dBa[i]);
            float combined = masking + ata[i];
            float w  = __log10f(ptB[i] / (combined + 1e-12f) + 1.0f);
            float d  = sqrtf(ppB[i]) - sqrtf(ptB[i]);
            contrib += w * d * d;
        }
    }
    if (j == 63) {                          // bin 256: never tonal, A-side only
        {
            float combined = ApA[3] * dA256 + at256;
            float w  = __log10f(ptA6 / (combined + 1e-12f) + 1.0f);
            float d  = sqrtf(ppA6) - sqrtf(ptA6);
            contrib += w * d * d;
        }
        {
            float combined = ApB[3] * dA256 + at256;
            float w  = __log10f(ptB6 / (combined + 1e-12f) + 1.0f);
            float d  = sqrtf(ppB6) - sqrtf(ptB6);
            contrib += w * d * d;
        }
    }

    // ---- block reduction (2 warps) ----
    float v = contrib;
    #pragma unroll
    for (int off = 16; off > 0; off >>= 1)
        v += __shfl_down_sync(0xffffffffu, v, off);
    if (lane == 0) redw[fw] = v;
    __syncthreads();
    const int bid = blockIdx.y * (NT / NFR) + blockIdx.x;
    if (j == 0)
        g_partial[bid] = redw[0] + redw[1];

    // ---- last block: deterministic global reduction ----
    __threadfence();
    if (j == 0) {
        unsigned r = atomicAdd(&g_count, 1u);
        s_last = (r == NBLKS - 1) ? 1 : 0;
    }
    __syncthreads();
    if (s_last) {
        float s = 0.0f;
        for (int i = j; i < NBLKS; i += NTHREADS) s += g_partial[i];
        #pragma unroll
        for (int off = 16; off > 0; off >>= 1)
            s += __shfl_down_sync(0xffffffffu, s, off);
        if (lane == 0) redw[fw] = s;
        __syncthreads();
        if (j == 0) {
            out[0] = (redw[0] + redw[1]) * (1.0f / (float)(BATCH * NBINS * NT));
            g_count = 0;
        }
    }
}

extern "C" void kernel_launch(void* const* d_in, const int* in_sizes, int n_in,
                              void* d_out, int out_size) {
    const float* pred = (const float*)d_in[0];
    const float* tgt  = (const float*)d_in[1];
    float* out = (float*)d_out;
    dim3 grid(NT / NFR, BATCH);
    pam_kernel<<<grid, NTHREADS>>>(pred, tgt, out);
}

// round 13
// speedup vs baseline: 1.2468x; 1.2468x over previous
#include <cuda_runtime.h>
#include <math.h>

#define NFFT   512
#define HOP    480
#define NBINS  257
#define BATCH  8
#define LSIG   88200
#define NT     184
#define NFR    4                      // frames per block (2 groups x 2 frames)
#define NTHREADS 128
#define NBLKS  (BATCH * NT / NFR)     // 368 blocks
#define BARKMID 12.37

__device__ float g_partial[NBLKS];
__device__ unsigned int g_count = 0;

// ===========================================================================
// constexpr fp64 math (compile-time) — series-based, ~1e-14 accurate
// ===========================================================================
constexpr double c_sqrt(double x) {
    double g = x > 1.0 ? x : 1.0;
    for (int i = 0; i < 80; i++) g = 0.5 * (g + x / g);
    return g;
}
constexpr double c_exp(double x) {
    const double ln2 = 0.69314718055994530942;
    int k = (int)(x / ln2 + (x >= 0 ? 0.5 : -0.5));
    double r = x - (double)k * ln2;
    double term = 1.0, sum = 1.0;
    for (int i = 1; i <= 22; i++) { term *= r / (double)i; sum += term; }
    double p = 1.0;
    if (k >= 0) { for (int i = 0; i < k;  i++) p *= 2.0; }
    else        { for (int i = 0; i < -k; i++) p *= 0.5; }
    return sum * p;
}
constexpr double c_log(double x) {
    int k = 0; double m = x;
    while (m >= 2.0) { m *= 0.5; k++; }
    while (m < 1.0)  { m *= 2.0; k--; }
    double t = (m - 1.0) / (m + 1.0), t2 = t * t, term = t, sum = 0.0;
    for (int i = 0; i < 45; i++) { sum += term / (double)(2 * i + 1); term *= t2; }
    return 2.0 * sum + (double)k * 0.69314718055994530942;
}
constexpr double c_pow(double x, double y) { return c_exp(y * c_log(x)); }
constexpr double c_atan(double x) {
    if (x < 0.0) return -c_atan(-x);
    if (x > 1.0) return 1.57079632679489661923 - c_atan(1.0 / x);
    double x1 = x  / (1.0 + c_sqrt(1.0 + x  * x));
    double x2 = x1 / (1.0 + c_sqrt(1.0 + x1 * x1));
    double t2 = x2 * x2, term = x2, sum = 0.0;
    for (int i = 0; i < 26; i++) {
        sum += ((i & 1) ? -term : term) / (double)(2 * i + 1);
        term *= t2;
    }
    return 4.0 * sum;
}
constexpr double c_cospi(double x) {
    double y = x;
    while (y >= 2.0) y -= 2.0;
    while (y < 0.0)  y += 2.0;
    double sign = 1.0;
    if (y > 1.0) y = 2.0 - y;
    if (y > 0.5) { y = 1.0 - y; sign = -1.0; }
    double a = y * 3.14159265358979323846;
    double a2 = a * a, term = 1.0, sum = 0.0;
    for (int i = 0; i < 16; i++) { sum += term; term *= -a2 / (double)((2 * i + 1) * (2 * i + 2)); }
    return sign * sum;
}
constexpr double c_sinpi(double x) { return c_cospi(x - 0.5); }
constexpr double c_bark(int i) {
    double freq = (double)i * (44100.0 / 512.0);
    double r = freq / 7500.0;
    return 13.0 * c_atan(0.00076 * freq) + 3.5 * c_atan(r * r);
}

// Flat table blob: win[512] | tw[7][64] (float2) | cA dA cB dB ath (260 ea)
#define OFF_WIN 0
#define OFF_TW  512
#define OFF_CA  1408
#define OFF_DA  1668
#define OFF_CB  1928
#define OFF_DB  2188
#define OFF_ATH 2448
#define TABN4   2708
#define NTW     (7 * 64)

struct AllTabs { alignas(16) float v[TABN4]; };

constexpr AllTabs mk_tabs() {
    AllTabs t{};
    for (int i = 0; i < NFFT; i++)
        t.v[OFF_WIN + i] = (float)(0.5 * (1.0 - c_cospi((double)i / 256.0)));
    for (int r = 0; r < 7; r++)
        for (int j = 0; j < 64; j++) {
            double ang = (double)(j * (r + 1)) / 256.0;
            t.v[OFF_TW + 2 * (r * 64 + j) + 0] = (float)c_cospi(ang);
            t.v[OFF_TW + 2 * (r * 64 + j) + 1] = (float)(-c_sinpi(ang));  // conj
        }
    const double LN10 = 2.30258509299404568402;
    for (int i = 0; i < NBINS; i++) {
        double d = (c_bark(i) - BARKMID) * LN10;
        t.v[OFF_CA + i] = (float)c_exp( 1.7 * d);
        t.v[OFF_DA + i] = (float)c_exp(-1.7 * d);
        t.v[OFF_CB + i] = (float)c_exp(-2.7 * d);
        t.v[OFF_DB + i] = (float)c_exp( 2.7 * d);
        double freq = (double)i * (44100.0 / 512.0);
        double f = freq > 1e-6 ? freq : 1e-6;
        double fk = f / 1000.0;
        double ath_db = 3.64 * c_pow(fk, -0.8)
                      - 6.5 * c_exp(-0.6 * (fk - 3.3) * (fk - 3.3))
                      + 0.001 * fk * fk * fk * fk;
        if (ath_db > 100.0) ath_db = 100.0;
        if (ath_db < -100.0) ath_db = -100.0;
        double a = c_exp(ath_db * 0.1 * LN10);
        if (a < 1e-12) a = 1e-12;
        t.v[OFF_ATH + i] = (float)a;
    }
    return t;
}
__device__ const AllTabs g_tabs = mk_tabs();

// ===========================================================================
__device__ __forceinline__ float2 cadd(float2 a, float2 b) { return make_float2(a.x + b.x, a.y + b.y); }
__device__ __forceinline__ float2 csub(float2 a, float2 b) { return make_float2(a.x - b.x, a.y - b.y); }
__device__ __forceinline__ float2 cmul(float2 a, float2 b) {
    return make_float2(fmaf(a.x, b.x, -a.y * b.y), fmaf(a.x, b.y, a.y * b.x));
}

__device__ __forceinline__ void dft8(float2* x) {
    const float C = 0.70710678118654752f;
    float2 a0 = cadd(x[0], x[4]), a4 = csub(x[0], x[4]);
    float2 a2 = cadd(x[2], x[6]), a6 = csub(x[2], x[6]);
    float2 a1 = cadd(x[1], x[5]), a5 = csub(x[1], x[5]);
    float2 a3 = cadd(x[3], x[7]), a7 = csub(x[3], x[7]);
    float2 b0 = cadd(a0, a2), b2 = csub(a0, a2);
    float2 b1 = cadd(a1, a3), b3 = csub(a1, a3);
    float2 b4 = make_float2(a4.x + a6.y, a4.y - a6.x);
    float2 b6 = make_float2(a4.x - a6.y, a4.y + a6.x);
    float2 b5 = make_float2(a5.x + a7.y, a5.y - a7.x);
    float2 b7 = make_float2(a5.x - a7.y, a5.y + a7.x);
    x[0] = cadd(b0, b1);  x[4] = csub(b0, b1);
    x[2] = make_float2(b2.x + b3.y, b2.y - b3.x);
    x[6] = make_float2(b2.x - b3.y, b2.y + b3.x);
    float2 t5 = make_float2(C * (b5.x + b5.y), C * (b5.y - b5.x));
    x[1] = cadd(b4, t5);  x[5] = csub(b4, t5);
    float2 t7 = make_float2(C * (b7.y - b7.x), -C * (b7.x + b7.y));
    x[3] = cadd(b6, t7);  x[7] = csub(b6, t7);
}

#define PHYS(i) ((i) + ((i) >> 3))
#define BARF(id) asm volatile("bar.sync %0, %1;" :: "r"((id) + 1), "r"(64) : "memory")

__global__ __launch_bounds__(NTHREADS) void pam_kernel(
    const float* __restrict__ pred, const float* __restrict__ tgt,
    float* __restrict__ out)
{
    __shared__ float4 Zs[2][576];               // .xy frame A, .zw frame B
    __shared__ float2 sTw[NTW];
    __shared__ __align__(16) float pts[NFR][260];
    __shared__ float sAg[NFR], sBg[NFR];
    __shared__ float redw[4];
    __shared__ int   s_last;

    const int tid  = threadIdx.x;
    const int gid  = tid >> 6;             // frame-pair group (0/1)
    const int j    = tid & 63;
    const int lane = tid & 31;
    const int wrp  = tid >> 5;             // 0..3
    const int fw   = wrp & 1;              // warp within group
    const int fA   = 2 * gid;
    const int fB   = 2 * gid + 1;

    const int b = blockIdx.y;
    const int tb = (NFR * blockIdx.x + 2 * gid) * HOP - (NFFT / 2);

    // ---- stage twiddles to shared (3.5KB, coalesced float4) ----
    {
        const float4* src = (const float4*)&g_tabs.v[OFF_TW];
        float4* dst = (float4*)sTw;
        #pragma unroll
        for (int i = tid; i < NTW / 2; i += NTHREADS) dst[i] = src[i];
    }

    // ---- window taps (coalesced float4) ----
    const float4 wlo = *(const float4*)&g_tabs.v[OFF_WIN + 4 * j];
    const float4 whi = *(const float4*)&g_tabs.v[OFF_WIN + 256 + 4 * j];

    // ---- vectorized sample loads: thread j owns n = 4j..4j+3 and 256+4j..+3 ----
    const float* xp = pred + b * LSIG;
    const float* xt = tgt  + b * LSIG;
    float laP[4], laT[4], haP[4], haT[4];
    float lbP[4], lbT[4], hbP[4], hbT[4];
    if (blockIdx.x == 0 && gid == 0) {
        // frame A low half needs reflect (tb = -256); scalar path
        #pragma unroll
        for (int i = 0; i < 4; i++) {
            int g = tb + 4 * j + i;
            if (g < 0) g = -g;
            laP[i] = xp[g]; laT[i] = xt[g];
        }
    } else {
        float4 v1 = *(const float4*)(xp + tb + 4 * j);
        float4 v2 = *(const float4*)(xt + tb + 4 * j);
        laP[0] = v1.x; laP[1] = v1.y; laP[2] = v1.z; laP[3] = v1.w;
        laT[0] = v2.x; laT[1] = v2.y; laT[2] = v2.z; laT[3] = v2.w;
    }
    {   // frame A high half (always in-range: tb+256 >= 0)
        float4 v1 = *(const float4*)(xp + tb + 256 + 4 * j);
        float4 v2 = *(const float4*)(xt + tb + 256 + 4 * j);
        haP[0] = v1.x; haP[1] = v1.y; haP[2] = v1.z; haP[3] = v1.w;
        haT[0] = v2.x; haT[1] = v2.y; haT[2] = v2.z; haT[3] = v2.w;
    }
    {   // frame B (always in-range: tb+HOP >= 224, end <= 88095)
        float4 v1 = *(const float4*)(xp + tb + HOP + 4 * j);
        float4 v2 = *(const float4*)(xt + tb + HOP + 4 * j);
        lbP[0] = v1.x; lbP[1] = v1.y; lbP[2] = v1.z; lbP[3] = v1.w;
        lbT[0] = v2.x; lbT[1] = v2.y; lbT[2] = v2.z; lbT[3] = v2.w;
        float4 v3 = *(const float4*)(xp + tb + HOP + 256 + 4 * j);
        float4 v4 = *(const float4*)(xt + tb + HOP + 256 + 4 * j);
        hbP[0] = v3.x; hbP[1] = v3.y; hbP[2] = v3.z; hbP[3] = v3.w;
        hbT[0] = v4.x; hbT[1] = v4.y; hbT[2] = v4.z; hbT[3] = v4.w;
    }
    const float wl[4] = { wlo.x, wlo.y, wlo.z, wlo.w };
    const float wh[4] = { whi.x, whi.y, whi.z, whi.w };
    #pragma unroll
    for (int i = 0; i < 4; i++) {
        int n = 4 * j + i;
        Zs[gid][PHYS(n)]       = make_float4(laP[i] * wl[i], laT[i] * wl[i],
                                             lbP[i] * wl[i], lbT[i] * wl[i]);
        Zs[gid][PHYS(n + 256)] = make_float4(haP[i] * wh[i], haT[i] * wh[i],
                                             hbP[i] * wh[i], hbT[i] * wh[i]);
    }
    __syncthreads();                       // sTw + Zs ready (block-wide: sTw shared by groups)

    // ---- pass 0: Lc=512, stride 64, twiddle tw[r][j] ----
    {
        float2 xa[8], xb[8];
        #pragma unroll
        for (int m = 0; m < 8; m++) {
            float4 v = Zs[gid][PHYS(j + (m << 6))];
            xa[m] = make_float2(v.x, v.y);
            xb[m] = make_float2(v.z, v.w);
        }
        dft8(xa); dft8(xb);
        #pragma unroll
        for (int r = 1; r < 8; r++) {
            float2 w = sTw[(r - 1) * 64 + j];
            xa[r] = cmul(xa[r], w);
            xb[r] = cmul(xb[r], w);
        }
        #pragma unroll
        for (int r = 0; r < 8; r++)
            Zs[gid][PHYS(j + (r << 6))] = make_float4(xa[r].x, xa[r].y, xb[r].x, xb[r].y);
    }
    BARF(gid);

    // ---- pass 1: Lc=64, stride 8, twiddle W64^(p*r) = tw[r][8p] ----
    {
        int p = j & 7;
        int base = ((j >> 3) << 6) + p;
        float2 xa[8], xb[8];
        #pragma unroll
        for (int m = 0; m < 8; m++) {
            float4 v = Zs[gid][PHYS(base + (m << 3))];
            xa[m] = make_float2(v.x, v.y);
            xb[m] = make_float2(v.z, v.w);
        }
        dft8(xa); dft8(xb);
        #pragma unroll
        for (int r = 1; r < 8; r++) {
            float2 w = sTw[(r - 1) * 64 + (p << 3)];
            xa[r] = cmul(xa[r], w);
            xb[r] = cmul(xb[r], w);
        }
        #pragma unroll
        for (int r = 0; r < 8; r++)
            Zs[gid][PHYS(base + (r << 3))] = make_float4(xa[r].x, xa[r].y, xb[r].x, xb[r].y);
    }
    BARF(gid);

    // ---- pass 2: Lc=8, contiguous (phys = 9j+m), no twiddle ----
    {
        float2 xa[8], xb[8];
        #pragma unroll
        for (int m = 0; m < 8; m++) {
            float4 v = Zs[gid][9 * j + m];
            xa[m] = make_float2(v.x, v.y);
            xb[m] = make_float2(v.z, v.w);
        }
        dft8(xa); dft8(xb);
        #pragma unroll
        for (int m = 0; m < 8; m++)
            Zs[gid][9 * j + m] = make_float4(xa[m].x, xa[m].y, xb[m].x, xb[m].y);
    }
    BARF(gid);

    // ---- psycho tables: issue now; the unpack below hides their latency ----
    const float4 cA4 = *(const float4*)&g_tabs.v[OFF_CA  + 4 * j];
    const float4 cB4 = *(const float4*)&g_tabs.v[OFF_CB  + 4 * j];
    const float4 dA4 = *(const float4*)&g_tabs.v[OFF_DA  + 4 * j];
    const float4 dB4 = *(const float4*)&g_tabs.v[OFF_DB  + 4 * j];
    const float4 at4 = *(const float4*)&g_tabs.v[OFF_ATH + 4 * j];
    const float dA256 = g_tabs.v[OFF_DA + 256];
    const float at256 = g_tabs.v[OFF_ATH + 256];

    // ---- unpack both real spectra for both frames; bins 4j..4j+3 ----
    float ppA[4], ptA[4], ppB[4], ptB[4];
    #pragma unroll
    for (int i = 0; i < 4; i++) {
        int k  = 4 * j + i;
        int pk = ((k & 7) << 6) | (k & 56) | (k >> 6);
        int kc = (NFFT - k) & (NFFT - 1);
        int pc = ((kc & 7) << 6) | (kc & 56) | (kc >> 6);
        float4 zk = Zs[gid][PHYS(pk)];
        float4 zc = Zs[gid][PHYS(pc)];
        {
            float spr = zk.x + zc.x, spi = zk.y - zc.y;
            float str = zk.y + zc.y, sti = zc.x - zk.x;
            ppA[i] = 0.25f * (spr * spr + spi * spi) + 1e-12f;
            ptA[i] = 0.25f * (str * str + sti * sti) + 1e-12f;
        }
        {
            float spr = zk.z + zc.z, spi = zk.w - zc.w;
            float str = zk.w + zc.w, sti = zc.z - zk.z;
            ppB[i] = 0.25f * (spr * spr + spi * spi) + 1e-12f;
            ptB[i] = 0.25f * (str * str + sti * sti) + 1e-12f;
        }
    }
    *(float4*)&pts[fA][4 * j] = make_float4(ptA[0], ptA[1], ptA[2], ptA[3]);
    *(float4*)&pts[fB][4 * j] = make_float4(ptB[0], ptB[1], ptB[2], ptB[3]);

    float ppA6 = 0.f, ptA6 = 0.f, ppB6 = 0.f, ptB6 = 0.f;
    if (j == 63) {                          // bin 256 at digit-reversed pos 4
        float4 z6 = Zs[gid][PHYS(4)];
        ppA6 = z6.x * z6.x + 1e-12f;  ptA6 = z6.y * z6.y + 1e-12f;
        ppB6 = z6.z * z6.z + 1e-12f;  ptB6 = z6.w * z6.w + 1e-12f;
        pts[fA][256] = ptA6;
        pts[fB][256] = ptB6;
    }
    BARF(gid);

    // ---- tonal detection + scaled linear masker terms (both frames) ----
    const float cAa[4] = { cA4.x, cA4.y, cA4.z, cA4.w };
    const float cBa[4] = { cB4.x, cB4.y, cB4.z, cB4.w };

    float aA[4], bA[4], aB[4], bB[4];
    {
        float pprevA = (j == 0) ? 3.4e38f : pts[fA][4 * j - 1];
        float pnextA = pts[fA][4 * j + 4];
        float pprevB = (j == 0) ? 3.4e38f : pts[fB][4 * j - 1];
        float pnextB = pts[fB][4 * j + 4];
        #pragma unroll
        for (int i = 0; i < 4; i++) {
            int k = 4 * j + i;
            float pA = ptA[i];
            float plA = (i == 0) ? pprevA : ptA[i - 1];
            float prA = (i == 3) ? pnextA : ptA[i + 1];
            bool tA = (k >= 1) && (pA > plA) && (pA > prA) && (pA >= 1e-4f);
            aA[i] = tA ? pA * cAa[i] : 0.0f;
            bA[i] = tA ? pA * cBa[i] : 0.0f;
            float pB = ptB[i];
            float plB = (i == 0) ? pprevB : ptB[i - 1];
            float prB = (i == 3) ? pnextB : ptB[i + 1];
            bool tB = (k >= 1) && (pB > plB) && (pB > prB) && (pB >= 1e-4f);
            aB[i] = tB ? pB * cAa[i] : 0.0f;
            bB[i] = tB ? pB * cBa[i] : 0.0f;
        }
    }

    // local prefix/suffix per frame
    float paA0 = aA[0], paA1 = fmaxf(paA0, aA[1]), paA2 = fmaxf(paA1, aA[2]), paA3 = fmaxf(paA2, aA[3]);
    float sbA3 = bA[3], sbA2 = fmaxf(sbA3, bA[2]), sbA1 = fmaxf(sbA2, bA[1]), sbA0 = fmaxf(sbA1, bA[0]);
    float paB0 = aB[0], paB1 = fmaxf(paB0, aB[1]), paB2 = fmaxf(paB1, aB[2]), paB3 = fmaxf(paB2, aB[3]);
    float sbB3 = bB[3], sbB2 = fmaxf(sbB3, bB[2]), sbB1 = fmaxf(sbB2, bB[1]), sbB0 = fmaxf(sbB1, bB[0]);

    // warp inclusive scans (forward A-terms, reverse B-terms), both frames
    float incA = paA3, incB = paB3;
    #pragma unroll
    for (int off = 1; off < 32; off <<= 1) {
        float oA = __shfl_up_sync(0xffffffffu, incA, off);
        float oB = __shfl_up_sync(0xffffffffu, incB, off);
        if (lane >= off) { incA = fmaxf(incA, oA); incB = fmaxf(incB, oB); }
    }
    float exAA = __shfl_up_sync(0xffffffffu, incA, 1);
    float exAB = __shfl_up_sync(0xffffffffu, incB, 1);
    if (lane == 0) { exAA = 0.0f; exAB = 0.0f; }
    if (fw == 0 && lane == 31) { sAg[fA] = incA; sAg[fB] = incB; }

    float rincA = sbA0, rincB = sbB0;
    #pragma unroll
    for (int off = 1; off < 32; off <<= 1) {
        float oA = __shfl_down_sync(0xffffffffu, rincA, off);
        float oB = __shfl_down_sync(0xffffffffu, rincB, off);
        if (lane + off < 32) { rincA = fmaxf(rincA, oA); rincB = fmaxf(rincB, oB); }
    }
    float exBA = __shfl_down_sync(0xffffffffu, rincA, 1);
    float exBB = __shfl_down_sync(0xffffffffu, rincB, 1);
    if (lane == 31) { exBA = 0.0f; exBB = 0.0f; }
    if (fw == 1 && lane == 0) { sBg[fA] = rincA; sBg[fB] = rincB; }
    BARF(gid);

    if (fw == 1) { exAA = fmaxf(exAA, sAg[fA]); exAB = fmaxf(exAB, sAg[fB]); }
    if (fw == 0) { exBA = fmaxf(exBA, sBg[fA]); exBB = fmaxf(exBB, sBg[fB]); }

    // ---- per-bin masking, weights, error (both frames) ----
    float ApA[4] = { fmaxf(exAA, paA0), fmaxf(exAA, paA1), fmaxf(exAA, paA2), fmaxf(exAA, paA3) };
    float BsA[4] = { fmaxf(exBA, sbA0), fmaxf(exBA, sbA1), fmaxf(exBA, sbA2), fmaxf(exBA, sbA3) };
    float ApB[4] = { fmaxf(exAB, paB0), fmaxf(exAB, paB1), fmaxf(exAB, paB2), fmaxf(exAB, paB3) };
    float BsB[4] = { fmaxf(exBB, sbB0), fmaxf(exBB, sbB1), fmaxf(exBB, sbB2), fmaxf(exBB, sbB3) };

    const float dAa[4] = { dA4.x, dA4.y, dA4.z, dA4.w };
    const float dBa[4] = { dB4.x, dB4.y, dB4.z, dB4.w };
    const float ata[4] = { at4.x, at4.y, at4.z, at4.w };

    float contrib = 0.0f;
    #pragma unroll
    for (int i = 0; i < 4; i++) {
        {
            float masking = fmaxf(ApA[i] * dAa[i], BsA[i] * dBa[i]);
            float combined = masking + ata[i];
            float w  = __log10f(ptA[i] / (combined + 1e-12f) + 1.0f);
            float d  = sqrtf(ppA[i]) - sqrtf(ptA[i]);
            contrib += w * d * d;
        }
        {
            float masking = fmaxf(ApB[i] * dAa[i], BsB[i] * dBa[i]);
            float combined = masking + ata[i];
            float w  = __log10f(ptB[i] / (combined + 1e-12f) + 1.0f);
            float d  = sqrtf(ppB[i]) - sqrtf(ptB[i]);
            contrib += w * d * d;
        }
    }
    if (j == 63) {                          // bin 256: never tonal, A-side only
        {
            float combined = ApA[3] * dA256 + at256;
            float w  = __log10f(ptA6 / (combined + 1e-12f) + 1.0f);
            float d  = sqrtf(ppA6) - sqrtf(ptA6);
            contrib += w * d * d;
        }
        {
            float combined = ApB[3] * dA256 + at256;
            float w  = __log10f(ptB6 / (combined + 1e-12f) + 1.0f);
            float d  = sqrtf(ppB6) - sqrtf(ptB6);
            contrib += w * d * d;
        }
    }

    // ---- block reduction (all 4 frames into one partial) ----
    float v = contrib;
    #pragma unroll
    for (int off = 16; off > 0; off >>= 1)
        v += __shfl_down_sync(0xffffffffu, v, off);
    if (lane == 0) redw[wrp] = v;
    __syncthreads();
    const int bid = blockIdx.y * (NT / NFR) + blockIdx.x;
    if (tid == 0)
        g_partial[bid] = redw[0] + redw[1] + redw[2] + redw[3];

    // ---- last block: deterministic global reduction ----
    __threadfence();
    if (tid == 0) {
        unsigned r = atomicAdd(&g_count, 1u);
        s_last = (r == NBLKS - 1) ? 1 : 0;
    }
    __syncthreads();
    if (s_last) {
        float s = 0.0f;
        for (int i = tid; i < NBLKS; i += NTHREADS) s += g_partial[i];
        #pragma unroll
        for (int off = 16; off > 0; off >>= 1)
            s += __shfl_down_sync(0xffffffffu, s, off);
        if (lane == 0) redw[wrp] = s;
        __syncthreads();
        if (tid == 0) {
            out[0] = (redw[0] + redw[1] + redw[2] + redw[3])
                   * (1.0f / (float)(BATCH * NBINS * NT));
            g_count = 0;
        }
    }
}

extern "C" void kernel_launch(void* const* d_in, const int* in_sizes, int n_in,
                              void* d_out, int out_size) {
    const float* pred = (const float*)d_in[0];
    const float* tgt  = (const float*)d_in[1];
    float* out = (float*)d_out;
    dim3 grid(NT / NFR, BATCH);
    pam_kernel<<<grid, NTHREADS>>>(pred, tgt, out);
}